// round 6
// baseline (speedup 1.0000x reference)
#include <cuda_runtime.h>
#include <cuda_fp16.h>
#include <cstdint>

#define T_SEQ    512
#define BATCH    4096
#define IND      64
#define HID      128
#define MT       32            // batch rows per CTA
#define NCTA     (BATCH / MT)  // 128
#define NKT      12            // k-tiles of 16 (K = 192)
#define NTHREADS 512           // 16 warps: 2 row-tiles x 8 col-groups (n=16/warp)
#define BUFU32   (2 * NKT * 128)   // u32 per A buffer

// ---------------------------------------------------------------------------

__device__ __forceinline__ uint32_t packh2(float a, float b) {
    __half2 h = __floats2half2_rn(a, b);
    return *reinterpret_cast<uint32_t*>(&h);
}

// D += A(16x16) * B(16x8)^T (row.col), fp16 in, fp32 accum
__device__ __forceinline__ void mma16(float* d, const uint32_t* a, uint32_t b0, uint32_t b1) {
    asm volatile(
        "mma.sync.aligned.m16n8k16.row.col.f32.f16.f16.f32 "
        "{%0,%1,%2,%3}, {%4,%5,%6,%7}, {%8,%9}, {%0,%1,%2,%3};"
        : "+f"(d[0]), "+f"(d[1]), "+f"(d[2]), "+f"(d[3])
        : "r"(a[0]), "r"(a[1]), "r"(a[2]), "r"(a[3]), "r"(b0), "r"(b1));
}

// accurate tanh: ex2.approx + rcp.approx, abs err ~1e-6, saturates at +-1
__device__ __forceinline__ float tanh_acc(float v) {
    float e = __expf(2.0f * v);
    return 1.0f - __fdividef(2.0f, e + 1.0f);
}

// u32 index of the half-PAIR (k, k+1) for row (0..31), k even (0..191)
// inside one A buffer laid out as [rt][kt][lane][4 regs] (m16n8k16 A frag).
__device__ __forceinline__ int xidx(int row, int k) {
    int kt = k >> 4, kk = k & 15;
    int lane = ((row & 7) << 2) | ((kk >> 1) & 3);
    int reg  = ((kk >> 3) << 1) | ((row >> 3) & 1);
    return ((row >> 4) * NKT + kt) * 128 + (lane << 2) + reg;
}

// ---------------------------------------------------------------------------

__global__ void __launch_bounds__(NTHREADS, 1)
rnn_kernel(const float* __restrict__ x, const float* __restrict__ Wih,
           const float* __restrict__ bih, const float* __restrict__ Whh,
           const float* __restrict__ bhh, float* __restrict__ out) {
    __shared__ uint32_t afrag[2][BUFU32];   // ping-pong A = [x_t | h_t] fp16 fragments

    const int tid = threadIdx.x;
    const int wid = tid >> 5;
    const int lid = tid & 31;
    const int rt  = wid >> 3;        // row tile: rows rt*16 .. +15
    const int cg  = wid & 7;         // col group: cols cg*16 .. +15 (2 n-tiles of 8)
    const int b0  = blockIdx.x * MT;

    // ---- B fragments (weights, fp16) resident in registers ----
    // n-tile nt = cg*2 + i: lane holds W[nt*8 + lid/4] at k = kt*16 + 2*(lid%4) + jb*8 (+1)
    uint32_t breg[2][NKT][2];
#pragma unroll
    for (int i = 0; i < 2; i++) {
        const int n = ((cg << 1) + i) * 8 + (lid >> 2);
        const float* wih_r = Wih + n * IND;
        const float* whh_r = Whh + n * HID;
#pragma unroll
        for (int kt = 0; kt < 4; kt++)      // k < 64: W_ih
#pragma unroll
            for (int jb = 0; jb < 2; jb++) {
                int k = (kt << 4) + ((lid & 3) << 1) + (jb << 3);
                breg[i][kt][jb] = packh2(wih_r[k], wih_r[k + 1]);
            }
#pragma unroll
        for (int kt = 4; kt < NKT; kt++)    // k >= 64: W_hh
#pragma unroll
            for (int jb = 0; jb < 2; jb++) {
                int k = (kt << 4) + ((lid & 3) << 1) + (jb << 3) - IND;
                breg[i][kt][jb] = packh2(whh_r[k], whh_r[k + 1]);
            }
    }

    // bias pairs in registers: output cols c0(i) = cg*16 + i*8 + (lid&3)*2
    float2 bb[2];
#pragma unroll
    for (int i = 0; i < 2; i++) {
        const int c0 = (cg << 4) + (i << 3) + ((lid & 3) << 1);
        bb[i].x = bih[c0]     + bhh[c0];
        bb[i].y = bih[c0 + 1] + bhh[c0 + 1];
    }

    // ---- init buffer 0: zeros (h_{-1}=0) + x_0 ----
    for (int i = tid; i < BUFU32; i += NTHREADS) afrag[0][i] = 0u;
    __syncthreads();

    // x handling: 1 float4 load/thread/step, scattered as 2 half2 stores
    const int xrow = tid >> 4;            // 0..31
    const int xk0  = (tid & 15) << 2;     // 0,4,..,60
    const int xw0  = xidx(xrow, xk0);
    const int xw1  = xidx(xrow, xk0 + 2);
    const float* xptr = x + (size_t)(b0 + xrow) * IND + xk0;
    {
        float4 xv = *(const float4*)xptr;
        afrag[0][xw0] = packh2(xv.x, xv.y);
        afrag[0][xw1] = packh2(xv.z, xv.w);
    }
    __syncthreads();

    const int rbase = (rt << 4) + (lid >> 2);   // low row of this lane
    const int hslab = 4 + cg;                   // h k-tile owned by this cg

    for (int t = 0; t < T_SEQ; t++) {
        // prefetch x_{t+1} (hidden under MMA phase)
        float4 xv;
        if (t + 1 < T_SEQ)
            xv = *(const float4*)(xptr + (size_t)(t + 1) * BATCH * IND);

        // ---- MMA: D = [x_t | h] @ [W_ih | W_hh]^T, K = 192 (12 fp16 k-tiles) ----
        const uint32_t* ar = afrag[t & 1] + rt * NKT * 128;
        float d[2][4] = {{0.f,0.f,0.f,0.f},{0.f,0.f,0.f,0.f}};
#pragma unroll
        for (int kt = 0; kt < NKT; kt++) {
            uint4 av = *(const uint4*)(ar + kt * 128 + (lid << 2));  // LDS.128, conflict-free
            mma16(d[0], (const uint32_t*)&av, breg[0][kt][0], breg[0][kt][1]);
            mma16(d[1], (const uint32_t*)&av, breg[1][kt][0], breg[1][kt][1]);
        }

        // ---- epilogue: bias + tanh ----
        float v[2][4];
#pragma unroll
        for (int i = 0; i < 2; i++) {
            v[i][0] = tanh_acc(d[i][0] + bb[i].x);   // (rbase,   c0)
            v[i][1] = tanh_acc(d[i][1] + bb[i].y);   // (rbase,   c0+1)
            v[i][2] = tanh_acc(d[i][2] + bb[i].x);   // (rbase+8, c0)
            v[i][3] = tanh_acc(d[i][3] + bb[i].y);   // (rbase+8, c0+1)
        }

        if (t + 1 < T_SEQ) {
            // write h_t + x_{t+1} into the OTHER buffer; one barrier per step.
            // The 2 n-tiles of this cg fill all 4 regs of slab (rt, 4+cg) at
            // lane' == lid  ->  exactly one STS.128 per thread, conflict-free.
            uint32_t* aw = afrag[(t + 1) & 1];
            uint4 pk;
            pk.x = packh2(v[0][0], v[0][1]);
            pk.y = packh2(v[0][2], v[0][3]);
            pk.z = packh2(v[1][0], v[1][1]);
            pk.w = packh2(v[1][2], v[1][3]);
            *(uint4*)(aw + (rt * NKT + hslab) * 128 + (lid << 2)) = pk;
            aw[xw0] = packh2(xv.x, xv.y);
            aw[xw1] = packh2(xv.z, xv.w);
            __syncthreads();
        } else {
            // final step: h_T (full fp32) to gmem
#pragma unroll
            for (int i = 0; i < 2; i++) {
                const int c0 = (cg << 4) + (i << 3) + ((lid & 3) << 1);
                *(float2*)(out + (size_t)(b0 + rbase) * HID + c0)
                    = make_float2(v[i][0], v[i][1]);
                *(float2*)(out + (size_t)(b0 + rbase + 8) * HID + c0)
                    = make_float2(v[i][2], v[i][3]);
            }
        }
    }
}

// ---------------------------------------------------------------------------

extern "C" void kernel_launch(void* const* d_in, const int* in_sizes, int n_in,
                              void* d_out, int out_size) {
    const float* x   = (const float*)d_in[0];
    const float* Wih = (const float*)d_in[1];
    const float* bih = (const float*)d_in[2];
    const float* Whh = (const float*)d_in[3];
    const float* bhh = (const float*)d_in[4];
    float* out = (float*)d_out;

    rnn_kernel<<<NCTA, NTHREADS>>>(x, Wih, bih, Whh, bhh, out);
}

// round 7
// speedup vs baseline: 1.9995x; 1.9995x over previous
#include <cuda_runtime.h>
#include <cuda_fp16.h>
#include <cstdint>

#define T_SEQ    512
#define BATCH    4096
#define IND      64
#define HID      128
#define MT       32            // batch rows per CTA
#define NCTA     (BATCH / MT)  // 128
#define NKT      12            // k-tiles of 16 (K = 192)
#define NTHREADS 256           // 8 warps: 2 row-tiles x 4 col-groups (n=32/warp)
#define BUFU32   (2 * NKT * 128)   // u32 per A buffer

// ---------------------------------------------------------------------------

__device__ __forceinline__ uint32_t packh2(float a, float b) {
    __half2 h = __floats2half2_rn(a, b);
    return *reinterpret_cast<uint32_t*>(&h);
}

// D += A(16x16) * B(16x8)^T (row.col), fp16 in, fp32 accum
__device__ __forceinline__ void mma16(float* d, const uint32_t* a, uint32_t b0, uint32_t b1) {
    asm volatile(
        "mma.sync.aligned.m16n8k16.row.col.f32.f16.f16.f32 "
        "{%0,%1,%2,%3}, {%4,%5,%6,%7}, {%8,%9}, {%0,%1,%2,%3};"
        : "+f"(d[0]), "+f"(d[1]), "+f"(d[2]), "+f"(d[3])
        : "r"(a[0]), "r"(a[1]), "r"(a[2]), "r"(a[3]), "r"(b0), "r"(b1));
}

// HW tanh (Turing+ MUFU.TANH): 1 op instead of 2 MUFU + 3 FMA
__device__ __forceinline__ float tanh_hw(float v) {
    float r;
    asm("tanh.approx.f32 %0, %1;" : "=f"(r) : "f"(v));
    return r;
}

// u32 index of the half-PAIR (k, k+1) for row (0..31), k even (0..191)
// inside one A buffer laid out as [rt][kt][lane][4 regs] (m16n8k16 A frag).
__device__ __forceinline__ int xidx(int row, int k) {
    int kt = k >> 4, kk = k & 15;
    int lane = ((row & 7) << 2) | ((kk >> 1) & 3);
    int reg  = ((kk >> 3) << 1) | ((row >> 3) & 1);
    return ((row >> 4) * NKT + kt) * 128 + (lane << 2) + reg;
}

// ---------------------------------------------------------------------------

__global__ void __launch_bounds__(NTHREADS, 1)
rnn_kernel(const float* __restrict__ x, const float* __restrict__ Wih,
           const float* __restrict__ bih, const float* __restrict__ Whh,
           const float* __restrict__ bhh, float* __restrict__ out) {
    __shared__ uint32_t afrag[2][BUFU32];   // ping-pong A = [x_t | h_t] fp16 fragments

    const int tid = threadIdx.x;
    const int wid = tid >> 5;
    const int lid = tid & 31;
    const int rt  = wid >> 2;        // row tile: rows rt*16 .. +15  (INDEPENDENT domains)
    const int cg  = wid & 3;         // col group: cols cg*32 .. +31 (4 n-tiles of 8)
    const int b0  = blockIdx.x * MT;

    // ---- B fragments (weights, fp16) resident in registers ----
    // n-tile nt = cg*4 + i: lane holds W[nt*8 + lid/4] at k = kt*16 + 2*(lid%4) + jb*8 (+1)
    uint32_t breg[4][NKT][2];
#pragma unroll
    for (int i = 0; i < 4; i++) {
        const int n = ((cg << 2) + i) * 8 + (lid >> 2);
        const float* wih_r = Wih + n * IND;
        const float* whh_r = Whh + n * HID;
#pragma unroll
        for (int kt = 0; kt < 4; kt++)      // k < 64: W_ih
#pragma unroll
            for (int jb = 0; jb < 2; jb++) {
                int k = (kt << 4) + ((lid & 3) << 1) + (jb << 3);
                breg[i][kt][jb] = packh2(wih_r[k], wih_r[k + 1]);
            }
#pragma unroll
        for (int kt = 4; kt < NKT; kt++)    // k >= 64: W_hh
#pragma unroll
            for (int jb = 0; jb < 2; jb++) {
                int k = (kt << 4) + ((lid & 3) << 1) + (jb << 3) - IND;
                breg[i][kt][jb] = packh2(whh_r[k], whh_r[k + 1]);
            }
    }

    // bias pairs in registers: output cols c0(i) = cg*32 + i*8 + (lid&3)*2
    float2 bb[4];
#pragma unroll
    for (int i = 0; i < 4; i++) {
        const int c0 = (cg << 5) + (i << 3) + ((lid & 3) << 1);
        bb[i].x = bih[c0]     + bhh[c0];
        bb[i].y = bih[c0 + 1] + bhh[c0 + 1];
    }

    // ---- init buffer 0: zeros (h_{-1}=0) + x_0 ----
    for (int i = tid; i < BUFU32; i += NTHREADS) afrag[0][i] = 0u;
    __syncthreads();

    // x handling, CONFINED to this thread's rt domain:
    // domain rt covers global float4 indices [rt*256, rt*256+256); thread
    // local l = tid&127 handles idx = rt*256 + l and + 128.
    const int xdl = tid & 127;
    int   xw0[2], xw1[2];
    const float* xptr[2];
#pragma unroll
    for (int j = 0; j < 2; j++) {
        int idx = rt * 256 + xdl + j * 128;
        int row = idx >> 4;                 // stays inside rows rt*16..+15
        int k0  = (idx & 15) << 2;
        xw0[j] = xidx(row, k0);
        xw1[j] = xidx(row, k0 + 2);
        xptr[j] = x + (size_t)(b0 + row) * IND + k0;
    }
#pragma unroll
    for (int j = 0; j < 2; j++) {
        float4 xv = *(const float4*)xptr[j];
        afrag[0][xw0[j]] = packh2(xv.x, xv.y);
        afrag[0][xw1[j]] = packh2(xv.z, xv.w);
    }
    __syncthreads();

    const int rbase = (rt << 4) + (lid >> 2);   // low row of this lane
    const int barid = 1 + rt;                   // per-domain named barrier

    for (int t = 0; t < T_SEQ; t++) {
        // prefetch x_{t+1} (hidden under MMA phase)
        float4 xv0, xv1;
        if (t + 1 < T_SEQ) {
            const size_t off = (size_t)(t + 1) * BATCH * IND;
            xv0 = *(const float4*)(xptr[0] + off);
            xv1 = *(const float4*)(xptr[1] + off);
        }

        // ---- MMA: D = [x_t | h] @ [W_ih | W_hh]^T, K = 192 (12 fp16 k-tiles) ----
        const uint32_t* ar = afrag[t & 1] + rt * NKT * 128;
        float d[4][4] = {{0.f,0.f,0.f,0.f},{0.f,0.f,0.f,0.f},
                         {0.f,0.f,0.f,0.f},{0.f,0.f,0.f,0.f}};
#pragma unroll
        for (int kt = 0; kt < NKT; kt++) {
            uint4 av = *(const uint4*)(ar + kt * 128 + (lid << 2));  // LDS.128, conflict-free
            mma16(d[0], (const uint32_t*)&av, breg[0][kt][0], breg[0][kt][1]);
            mma16(d[1], (const uint32_t*)&av, breg[1][kt][0], breg[1][kt][1]);
            mma16(d[2], (const uint32_t*)&av, breg[2][kt][0], breg[2][kt][1]);
            mma16(d[3], (const uint32_t*)&av, breg[3][kt][0], breg[3][kt][1]);
        }

        // ---- epilogue: bias + HW tanh ----
        float v[4][4];
#pragma unroll
        for (int i = 0; i < 4; i++) {
            v[i][0] = tanh_hw(d[i][0] + bb[i].x);   // (rbase,   c0)
            v[i][1] = tanh_hw(d[i][1] + bb[i].y);   // (rbase,   c0+1)
            v[i][2] = tanh_hw(d[i][2] + bb[i].x);   // (rbase+8, c0)
            v[i][3] = tanh_hw(d[i][3] + bb[i].y);   // (rbase+8, c0+1)
        }

        if (t + 1 < T_SEQ) {
            // write h_t + x_{t+1} into the OTHER buffer (own rt slabs only),
            // then sync ONLY this rt's 4 warps via named barrier.
            uint32_t* aw = afrag[(t + 1) & 1];
#pragma unroll
            for (int j = 0; j < 2; j++) {
                const int kt = 4 + (cg << 1) + j;    // h slabs of this cg
                uint4 pk;
                pk.x = packh2(v[2*j][0],   v[2*j][1]);
                pk.y = packh2(v[2*j][2],   v[2*j][3]);
                pk.z = packh2(v[2*j+1][0], v[2*j+1][1]);
                pk.w = packh2(v[2*j+1][2], v[2*j+1][3]);
                *(uint4*)(aw + (rt * NKT + kt) * 128 + (lid << 2)) = pk;  // STS.128
            }
            aw[xw0[0]] = packh2(xv0.x, xv0.y);
            aw[xw1[0]] = packh2(xv0.z, xv0.w);
            aw[xw0[1]] = packh2(xv1.x, xv1.y);
            aw[xw1[1]] = packh2(xv1.z, xv1.w);
            asm volatile("bar.sync %0, %1;" :: "r"(barid), "n"(128) : "memory");
        } else {
            // final step: h_T (full fp32) to gmem
#pragma unroll
            for (int i = 0; i < 4; i++) {
                const int c0 = (cg << 5) + (i << 3) + ((lid & 3) << 1);
                *(float2*)(out + (size_t)(b0 + rbase) * HID + c0)
                    = make_float2(v[i][0], v[i][1]);
                *(float2*)(out + (size_t)(b0 + rbase + 8) * HID + c0)
                    = make_float2(v[i][2], v[i][3]);
            }
        }
    }
}

// ---------------------------------------------------------------------------

extern "C" void kernel_launch(void* const* d_in, const int* in_sizes, int n_in,
                              void* d_out, int out_size) {
    const float* x   = (const float*)d_in[0];
    const float* Wih = (const float*)d_in[1];
    const float* bih = (const float*)d_in[2];
    const float* Whh = (const float*)d_in[3];
    const float* bhh = (const float*)d_in[4];
    float* out = (float*)d_out;

    rnn_kernel<<<NCTA, NTHREADS>>>(x, Wih, bih, Whh, bhh, out);
}